// round 8
// baseline (speedup 1.0000x reference)
#include <cuda_runtime.h>

#define NMOL 1024
#define MOLSIZE 128
#define MAXP 8128          // 128*127/2 upper-triangle max per molecule

// ---- static device scratch (no runtime allocation allowed) ----
__device__ int            g_atomCnt[NMOL];
__device__ int            g_pairCnt[NMOL];
__device__ int            g_atomBase[NMOL];
__device__ int            g_pairBase[NMOL];
__device__ int            g_nReal;
__device__ int            g_nPairs;
__device__ int            g_ticket = 0;
__device__ float4         g_pos4[NMOL * MOLSIZE];   // x,y,z, bits(sp | lrank<<8)
__device__ unsigned short g_pairList[NMOL * MAXP];  // (a<<8)|b row-major per molecule

// d2 threshold replicating (sqrtf(d2) < 5.0f): largest excluded d2 is 25-1ulp.
__device__ __forceinline__ float d2_thresh() { return __int_as_float(0x41C7FFFF); }

// bits strictly greater than a, restricted to 32-bit word w
__device__ __forceinline__ unsigned gt_mask(int a, int w) {
    const int aw = a >> 5;
    if (w < aw) return 0u;
    if (w > aw) return 0xffffffffu;
    return ~((2u << (a & 31)) - 1u);   // a&31==31 -> mask 0 (correct)
}

// ---- packed f32x2 helpers (sm_103a) ----
typedef unsigned long long ull;
__device__ __forceinline__ ull pack2(float lo, float hi) {
    ull r; asm("mov.b64 %0, {%1, %2};" : "=l"(r) : "f"(lo), "f"(hi)); return r;
}
__device__ __forceinline__ ull add2(ull a, ull b) {
    ull r; asm("add.rn.f32x2 %0, %1, %2;" : "=l"(r) : "l"(a), "l"(b)); return r;
}
__device__ __forceinline__ ull mul2(ull a, ull b) {
    ull r; asm("mul.rn.f32x2 %0, %1, %2;" : "=l"(r) : "l"(a), "l"(b)); return r;
}
__device__ __forceinline__ ull fma2(ull a, ull b, ull c) {
    ull r; asm("fma.rn.f32x2 %0, %1, %2, %3;" : "=l"(r) : "l"(a), "l"(b), "l"(c)); return r;
}
__device__ __forceinline__ void unpack2(float& lo, float& hi, ull v) {
    asm("mov.b64 {%0, %1}, %2;" : "=f"(lo), "=f"(hi) : "l"(v));
}

// ============================================================================
// K1: one molecule per 256-thread block. Triangle-only word-task sweep with
// packed f32x2 math (2 j's per iteration): coords in SoA shared so an LDS.64
// at even j yields a ready-packed pair; per-half rn semantics identical to the
// scalar version (a-b == a+(-b), same fma order) -> bit-identical masks.
// 10 warp-tasks (g,w>=g); each (a,w) mask word single-writer: no atomics.
// Fused cross-molecule scan via ticket in the last block.
// ============================================================================
__global__ void __launch_bounds__(256)
k_count(const int* __restrict__ species, const float* __restrict__ coords,
        const float* __restrict__ tore, float* __restrict__ out)
{
    __shared__ float    scx[MOLSIZE], scy[MOLSIZE], scz[MOLSIZE];
    __shared__ unsigned rmask[MOLSIZE][4];
    __shared__ unsigned nbw[4];
    __shared__ int      sWI[4][3];
    __shared__ float    sWF[4];
    __shared__ int      sWC[4];
    __shared__ int      sScanA[8], sScanB[8];
    __shared__ int      sLast;

    const int tid  = threadIdx.x;
    const int a    = tid & 127;
    const int lane = tid & 31;
    const int wid  = tid >> 5;          // 0..7
    const int m    = blockIdx.x;

    int   sp = 0;
    float x = 0.f, y = 0.f, z = 0.f;
    if (tid < 128) {
        sp = species[m * MOLSIZE + a];
        const float* cp = coords + (size_t)(m * MOLSIZE + a) * 3;
        x = cp[0]; y = cp[1]; z = cp[2];
        scx[a] = x; scy[a] = y; scz[a] = z;

        const unsigned bH = __ballot_sync(0xffffffffu, sp > 1);
        const unsigned bY = __ballot_sync(0xffffffffu, sp == 1);
        const unsigned bN = __ballot_sync(0xffffffffu, sp > 0);
        float f1 = tore[sp];
        #pragma unroll
        for (int o = 16; o; o >>= 1) f1 += __shfl_down_sync(0xffffffffu, f1, o);
        if (lane == 0) {
            sWI[wid][0] = __popc(bH); sWI[wid][1] = __popc(bY); sWI[wid][2] = __popc(bN);
            sWF[wid] = f1; nbw[wid] = bN;
        }
    }
    __syncthreads();

    if (tid == 0) {
        int H = 0, Y = 0, N = 0; float F = 0.0f;
        #pragma unroll
        for (int w = 0; w < 4; w++) { H += sWI[w][0]; Y += sWI[w][1]; N += sWI[w][2]; F += sWF[w]; }
        out[2 + m]          = (float)H;               // nHeavy
        out[2 + NMOL + m]   = (float)Y;               // nHydro
        out[2 + 2*NMOL + m] = (float)(int)(F * 0.5f); // nocc
        g_atomCnt[m] = N;
        if (m == 0) { out[0] = (float)NMOL; out[1] = (float)MOLSIZE; }
    }

    if (tid < 128) {                    // pos4 handoff: coords + packed sp|lrank
        int wb = 0;
        #pragma unroll
        for (int w = 0; w < 4; w++) if (w < wid) wb += __popc(nbw[w]);
        const int lrank = wb + __popc(nbw[wid] & ((1u << lane) - 1u));
        g_pos4[m * MOLSIZE + a] = make_float4(x, y, z, __int_as_float(sp | (lrank << 8)));
    }

    // ---- triangle word-task sweep, packed f32x2 (10 tasks over 8 warps) ----
    {
        const float th = d2_thresh();
        auto sweep = [&](int g, int w) {
            const int ar = g * 32 + lane;
            const float mx = scx[ar], my = scy[ar], mz = scz[ar];
            const ull nx2 = pack2(-mx, -mx);
            const ull ny2 = pack2(-my, -my);
            const ull nz2 = pack2(-mz, -mz);
            const int j0 = w * 32;
            unsigned msk = 0u;
            #pragma unroll
            for (int p = 0; p < 16; p++) {
                const int j = j0 + 2 * p;
                const ull jx = *(const ull*)(scx + j);   // LDS.64 broadcast (8B aligned)
                const ull jy = *(const ull*)(scy + j);
                const ull jz = *(const ull*)(scz + j);
                const ull dx2 = add2(jx, nx2);
                const ull dy2 = add2(jy, ny2);
                const ull dz2 = add2(jz, nz2);
                const ull d2p = fma2(dx2, dx2, fma2(dy2, dy2, mul2(dz2, dz2)));
                float dlo, dhi; unpack2(dlo, dhi, d2p);
                if (dlo < th) msk |= 1u << (2 * p);
                if (dhi < th) msk |= 1u << (2 * p + 1);
            }
            rmask[ar][w] = msk;
        };
        // primary tasks per warp: g digits 0,0,0,0,1,1,1,2 ; w digits 0,1,2,3,1,2,3,2
        sweep((int)((0x21110000u >> (wid * 4)) & 15u),
              (int)((0x23213210u >> (wid * 4)) & 15u));
        if (wid == 1) sweep(2, 3);      // extra task 9
        if (wid == 6) sweep(3, 3);      // extra task 10
    }
    __syncthreads();

    // ---- rows 0..127: post-mask, count, ordered scan ----
    unsigned r[4]; int excl = 0, cnt = 0;
    if (tid < 128) {
        const unsigned own = (nbw[a >> 5] >> (a & 31)) & 1u ? 0xffffffffu : 0u;
        #pragma unroll
        for (int w = 0; w < 4; w++) {
            r[w] = rmask[a][w] & gt_mask(a, w) & nbw[w] & own;
            cnt += __popc(r[w]);
        }
        int incl = cnt;
        #pragma unroll
        for (int o = 1; o < 32; o <<= 1) {
            int v = __shfl_up_sync(0xffffffffu, incl, o);
            if (lane >= o) incl += v;
        }
        if (lane == 31) sWC[wid] = incl;
        excl = incl - cnt;
    }
    __syncthreads();

    // ticket fires before the emit loop: the grid scan needs only the counts
    if (tid == 0) {
        g_pairCnt[m] = sWC[0] + sWC[1] + sWC[2] + sWC[3];
        __threadfence();
        const int old = atomicAdd(&g_ticket, 1);
        sLast = (old == (int)gridDim.x - 1);
    }

    if (tid < 128 && cnt) {
        int wb = 0;
        #pragma unroll
        for (int w = 0; w < 4; w++) if (w < wid) wb += sWC[w];
        excl += wb;
        unsigned short* dst = g_pairList + m * MAXP + excl;
        int k = 0;
        #pragma unroll
        for (int w = 0; w < 4; w++) {
            unsigned mm = r[w];
            while (mm) {
                int b = (w << 5) + __ffs((int)mm) - 1;
                mm &= mm - 1u;
                dst[k++] = (unsigned short)((a << 8) | b);
            }
        }
    }
    __syncthreads();

    // ---- last block: scan all 1024 counts ----
    if (sLast) {
        __threadfence();
        const int b4 = tid * 4;
        int oA[4], oB[4], sA = 0, sB = 0;
        #pragma unroll
        for (int q = 0; q < 4; q++) {
            oA[q] = g_atomCnt[b4 + q]; sA += oA[q];
            oB[q] = g_pairCnt[b4 + q]; sB += oB[q];
        }
        int ia = sA, ib = sB;
        #pragma unroll
        for (int o = 1; o < 32; o <<= 1) {
            int va = __shfl_up_sync(0xffffffffu, ia, o);
            int vb = __shfl_up_sync(0xffffffffu, ib, o);
            if (lane >= o) { ia += va; ib += vb; }
        }
        if (lane == 31) { sScanA[wid] = ia; sScanB[wid] = ib; }
        __syncthreads();
        int bA = 0, bB = 0;
        #pragma unroll
        for (int w = 0; w < 8; w++) if (w < wid) { bA += sScanA[w]; bB += sScanB[w]; }
        int pA = bA + ia - sA, pB = bB + ib - sB;
        #pragma unroll
        for (int q = 0; q < 4; q++) {
            g_atomBase[b4 + q] = pA; pA += oA[q];
            g_pairBase[b4 + q] = pB; pB += oB[q];
        }
        if (tid == 255) { g_nReal = pA; g_nPairs = pB; }
        if (tid == 0)   g_ticket = 0;    // reset for next graph replay
    }
}

// ============================================================================
// K2: scatter outputs; one molecule per 256-thread block. Single-LDG.128
// preamble via g_pos4; float-precomputed sp/rank kill per-pair I2F chains.
// ============================================================================
__global__ void __launch_bounds__(256)
k_write(float* __restrict__ out)
{
    __shared__ float4 sc[MOLSIZE];
    __shared__ float  sfsp[MOLSIZE];    // (float)species
    __shared__ float  sfrank[MOLSIZE];  // (float)global rank

    const int tid = threadIdx.x;
    const int m   = blockIdx.x;

    const int nReal = g_nReal;
    const int nP    = g_nPairs;
    const int P0    = 3074 + 3 * nReal;

    const int base = g_pairBase[m];
    const int cnt  = g_pairCnt[m];
    const unsigned short* pl = g_pairList + m * MAXP;
    const int ab0  = pl[tid];            // prefetch first pair (always in-bounds)

    if (tid < MOLSIZE) {
        const float4 p  = g_pos4[m * MOLSIZE + tid];
        const int info  = __float_as_int(p.w);
        const int sp    = info & 255;
        const int rank  = g_atomBase[m] + (info >> 8);
        sc[tid]     = p;
        sfsp[tid]   = (float)sp;
        sfrank[tid] = (float)rank;
        if (sp > 0) {
            out[3074 + rank]             = (float)sp;                                            // Z
            out[3074 + nReal + rank]     = (float)(tid * (MOLSIZE + 1) + m * MOLSIZE * MOLSIZE); // maskd
            out[3074 + 2 * nReal + rank] = (float)m;                                             // atom_molid
        }
    }
    __syncthreads();

    const float molf  = (float)m;
    const float mbase = (float)(m * (MOLSIZE * MOLSIZE));

    #pragma unroll 2
    for (int t = tid; t < cnt; t += 256) {
        const int ab = (t == tid) ? ab0 : pl[t];
        const int a2 = ab >> 8, b2 = ab & 255;
        const float4 pa = sc[a2], pb = sc[b2];
        const float dx = pb.x - pa.x, dy = pb.y - pa.y, dz = pb.z - pa.z;
        const float d2   = dx * dx + dy * dy + dz * dz;
        const float inv  = rsqrtf(d2);
        const float dist = d2 * inv;
        const int q = base + t;
        out[P0 + q]            = mbase + (float)(a2 * MOLSIZE + b2);  // mask
        out[P0 + nP + q]       = molf;                                // pair_molid
        out[P0 + 2 * nP + q]   = sfsp[a2];                            // ni
        out[P0 + 3 * nP + q]   = sfsp[b2];                            // nj
        out[P0 + 4 * nP + q]   = sfrank[a2];                          // idxi
        out[P0 + 5 * nP + q]   = sfrank[b2];                          // idxj
        out[P0 + 6 * nP + 3 * q + 0] = dx * inv;                      // xij
        out[P0 + 6 * nP + 3 * q + 1] = dy * inv;
        out[P0 + 6 * nP + 3 * q + 2] = dz * inv;
        out[P0 + 9 * nP + q]   = dist * 1.8897261258369282f;          // rij
    }
}

// ============================================================================
extern "C" void kernel_launch(void* const* d_in, const int* in_sizes, int n_in,
                              void* d_out, int out_size)
{
    const int*   species = (const int*)d_in[0];
    const float* coords  = (const float*)d_in[1];
    const float* tore    = (const float*)d_in[2];
    float*       out     = (float*)d_out;
    (void)in_sizes; (void)n_in; (void)out_size;

    k_count<<<NMOL, 256>>>(species, coords, tore, out);
    k_write<<<NMOL, 256>>>(out);
}